// round 6
// baseline (speedup 1.0000x reference)
#include <cuda_runtime.h>
#include <cuda_bf16.h>
#include <cuda_fp16.h>
#include <cstdint>
#include <cstddef>

#define NN   50000
#define NE   600000
#define C    128
#define NG   128
#define OUTC 10
#define NT   391          // ceil(NN/128) M-tiles

// ---------------- scratch (static device globals: allocation-free) ----------
__device__ float  g_h0[NN * C];        // layer-2 fp32 output (for pool)
__device__ __half g_x16[NN * C];       // fp16 shadow of x (gather l0)
__device__ __half g_h16[NN * C];       // fp16 h (gather l1/l2; reused)
__device__ float  g_inv[NN];
__device__ float  g_ginv[NG];
__device__ float  g_pool[NG * C];
// split feature buffers: per row 128 u32 words: [0..63]=hi bf16 pairs, [64..127]=lo pairs
__device__ uint4 g_aggs4[NN * 32];
__device__ uint4 g_hsA4[NN * 32];
__device__ uint4 g_hsB4[NN * 32];
// weights, split: [layer][src(2)][n(128)][128 u32 words], as uint4
__device__ uint4 g_Bp4[3][8192];
__device__ int   g_cnt[NN];
__device__ int   g_gcnt[NG];
__device__ int   g_off[NN + 1];
__device__ int   g_cur[NN];
__device__ int   g_adj[NE];
__device__ int   g_src[NE];
__device__ int   g_dst[NE];
__device__ int   g_batch[NN];
__device__ int   g_part[256];
__device__ int   g_pbase[256];
__device__ int   g_is64;

// ---------------- split helpers ---------------------------------------------
__device__ __forceinline__ void split2(float a, float b, uint32_t& hi, uint32_t& lo) {
    uint32_t ua = __float_as_uint(a);
    uint32_t ub = __float_as_uint(b);
    hi = __byte_perm(ua, ub, 0x7632);
    float ra = a - __uint_as_float(ua & 0xFFFF0000u);
    float rb = b - __uint_as_float(ub & 0xFFFF0000u);
    asm("cvt.rn.bf16x2.f32 %0, %1, %2;" : "=r"(lo) : "f"(rb), "f"(ra));
}

// ---------------- mma.sync bf16 m16n8k16 ------------------------------------
__device__ __forceinline__ void mma_bf16(float* d,
                                         uint32_t a0, uint32_t a1, uint32_t a2, uint32_t a3,
                                         uint32_t b0, uint32_t b1) {
    asm volatile(
        "mma.sync.aligned.m16n8k16.row.col.f32.bf16.bf16.f32 "
        "{%0,%1,%2,%3}, {%4,%5,%6,%7}, {%8,%9}, {%0,%1,%2,%3};"
        : "+f"(d[0]), "+f"(d[1]), "+f"(d[2]), "+f"(d[3])
        : "r"(a0), "r"(a1), "r"(a2), "r"(a3), "r"(b0), "r"(b1));
}

// ---------------- index dtype detection -------------------------------------
__global__ void detect_kernel(const unsigned int* __restrict__ ei_words) {
    int is64 = 1;
#pragma unroll
    for (int i = 0; i < 16; i++)
        if (ei_words[1 + 74 * i] != 0u) { is64 = 0; break; }
    g_is64 = is64;
}

// ---------------- zero pass --------------------------------------------------
__global__ void zero_setup() {
    int i = blockIdx.x * blockDim.x + threadIdx.x;
    if (i < NN) g_cnt[i] = 0;
    if (i < NG) g_gcnt[i] = 0;
    if (i < NG * C) g_pool[i] = 0.0f;
}

// ---------------- fused convert + degree + batch count ----------------------
__global__ void convert_fused(const void* __restrict__ ei, const void* __restrict__ batch) {
    int i = blockIdx.x * blockDim.x + threadIdx.x;
    const bool is64 = (g_is64 != 0);
    if (i < NE) {
        int s, d;
        if (is64) {
            const long long* p = (const long long*)ei;
            s = (int)p[i];
            d = (int)p[NE + i];
        } else {
            const int* p = (const int*)ei;
            s = p[i];
            d = p[NE + i];
        }
        g_src[i] = s;
        g_dst[i] = d;
        atomicAdd(&g_cnt[d], 1);
    }
    if (i < NN) {
        int b;
        if (is64) b = (int)((const long long*)batch)[i];
        else      b = ((const int*)batch)[i];
        g_batch[i] = b;
        atomicAdd(&g_gcnt[b], 1);
    }
}

// ---------------- 3-stage parallel scan --------------------------------------
__global__ void scan1() {
    __shared__ int red[256];
    const int tid = threadIdx.x;
    int i = blockIdx.x * 256 + tid;
    red[tid] = (i < NN) ? g_cnt[i] : 0;
    __syncthreads();
    for (int s = 128; s > 0; s >>= 1) {
        if (tid < s) red[tid] += red[tid + s];
        __syncthreads();
    }
    if (tid == 0) g_part[blockIdx.x] = red[0];
}

__global__ void scan2() {
    __shared__ int sc[256];
    const int t = threadIdx.x;
    int v = (t < 196) ? g_part[t] : 0;
    sc[t] = v;
    __syncthreads();
    for (int d = 1; d < 256; d <<= 1) {
        int val = sc[t];
        int add = (t >= d) ? sc[t - d] : 0;
        __syncthreads();
        sc[t] = val + add;
        __syncthreads();
    }
    if (t < 196) g_pbase[t] = sc[t] - v;
    if (t == 0) g_off[NN] = NE;
    if (t < NG) g_ginv[t] = 1.0f / fmaxf((float)g_gcnt[t], 1.0f);
}

__global__ void scan3() {
    __shared__ int sc[256];
    const int tid = threadIdx.x;
    int i = blockIdx.x * 256 + tid;
    int v = (i < NN) ? g_cnt[i] : 0;
    sc[tid] = v;
    __syncthreads();
    for (int d = 1; d < 256; d <<= 1) {
        int val = sc[tid];
        int add = (tid >= d) ? sc[tid - d] : 0;
        __syncthreads();
        sc[tid] = val + add;
        __syncthreads();
    }
    if (i < NN) {
        int excl = sc[tid] - v + g_pbase[blockIdx.x];
        g_off[i] = excl;
        g_cur[i] = excl;
        g_inv[i] = 1.0f / fmaxf((float)v, 1.0f);
    }
}

__global__ void fill_kernel() {
    int e = blockIdx.x * blockDim.x + threadIdx.x;
    if (e < NE) {
        int dst = g_dst[e];
        int pos = atomicAdd(&g_cur[dst], 1);
        g_adj[pos] = g_src[e];
    }
}

// ---------------- weight prep: split all layers ------------------------------
__global__ void prep_all(const float* __restrict__ Wl0, const float* __restrict__ Wr0,
                         const float* __restrict__ Wl1, const float* __restrict__ Wr1,
                         const float* __restrict__ Wl2, const float* __restrict__ Wr2) {
    int idx = blockIdx.x * blockDim.x + threadIdx.x;   // 3*16384
    if (idx >= 3 * 16384) return;
    int layer = idx >> 14;
    int rem = idx & 16383;
    int s = rem >> 13;
    int n = (rem >> 6) & 127;
    int w = rem & 63;
    const float* W;
    if (layer == 0)      W = s ? Wr0 : Wl0;
    else if (layer == 1) W = s ? Wr1 : Wl1;
    else                 W = s ? Wr2 : Wl2;
    float a = W[n * 128 + 2 * w];
    float b = W[n * 128 + 2 * w + 1];
    uint32_t hi, lo;
    split2(a, b, hi, lo);
    uint32_t* Bp = (uint32_t*)g_Bp4[layer];
    Bp[(s * 128 + n) * 128 + w] = hi;
    Bp[(s * 128 + n) * 128 + 64 + w] = lo;
}

// ---------------- split x into g_hsA + fp16 shadow into g_x16 ---------------
__global__ void split_x(const float* __restrict__ x) {
    int id = blockIdx.x * blockDim.x + threadIdx.x;  // NN*32
    if (id >= NN * 32) return;
    int node = id >> 5;
    int f4 = id & 31;
    const float4 v = *(const float4*)(x + (size_t)node * C + f4 * 4);
    uint32_t h0, l0, h1, l1;
    split2(v.x, v.y, h0, l0);
    split2(v.z, v.w, h1, l1);
    uint32_t* out = (uint32_t*)g_hsA4;
    *(uint2*)(out + (size_t)node * 128 + f4 * 2) = make_uint2(h0, h1);
    *(uint2*)(out + (size_t)node * 128 + 64 + f4 * 2) = make_uint2(l0, l1);
    __half2 p0 = __floats2half2_rn(v.x, v.y);
    __half2 p1 = __floats2half2_rn(v.z, v.w);
    *(uint2*)(g_x16 + (size_t)node * C + f4 * 4) =
        make_uint2(*(uint32_t*)&p0, *(uint32_t*)&p1);
}

// ---------------- mean aggregation (fp16 in, unroll x4) + fused split -------
__global__ void gather_kernel(int in_sel) {
    const __half* hin = (in_sel == 0) ? g_x16 : g_h16;
    int gid = blockIdx.x * blockDim.x + threadIdx.x;
    int node = gid >> 5;
    int lane = gid & 31;
    if (node >= NN) return;
    const int beg = g_off[node];
    const int end = g_off[node + 1];
    const int co = lane * 4;
    float4 a0 = make_float4(0.f, 0.f, 0.f, 0.f);
    float4 a1 = make_float4(0.f, 0.f, 0.f, 0.f);
    float4 a2 = make_float4(0.f, 0.f, 0.f, 0.f);
    float4 a3 = make_float4(0.f, 0.f, 0.f, 0.f);
    int i = beg;
    const int n4 = beg + ((end - beg) & ~3);
    for (; i < n4; i += 4) {
        int s0 = g_adj[i], s1 = g_adj[i + 1], s2 = g_adj[i + 2], s3 = g_adj[i + 3];
        uint2 u0 = *(const uint2*)(hin + (size_t)s0 * C + co);
        uint2 u1 = *(const uint2*)(hin + (size_t)s1 * C + co);
        uint2 u2 = *(const uint2*)(hin + (size_t)s2 * C + co);
        uint2 u3 = *(const uint2*)(hin + (size_t)s3 * C + co);
        float2 f;
        f = __half22float2(*(__half2*)&u0.x); a0.x += f.x; a0.y += f.y;
        f = __half22float2(*(__half2*)&u0.y); a0.z += f.x; a0.w += f.y;
        f = __half22float2(*(__half2*)&u1.x); a1.x += f.x; a1.y += f.y;
        f = __half22float2(*(__half2*)&u1.y); a1.z += f.x; a1.w += f.y;
        f = __half22float2(*(__half2*)&u2.x); a2.x += f.x; a2.y += f.y;
        f = __half22float2(*(__half2*)&u2.y); a2.z += f.x; a2.w += f.y;
        f = __half22float2(*(__half2*)&u3.x); a3.x += f.x; a3.y += f.y;
        f = __half22float2(*(__half2*)&u3.y); a3.z += f.x; a3.w += f.y;
    }
    for (; i < end; i++) {
        int s0 = g_adj[i];
        uint2 u0 = *(const uint2*)(hin + (size_t)s0 * C + co);
        float2 f;
        f = __half22float2(*(__half2*)&u0.x); a0.x += f.x; a0.y += f.y;
        f = __half22float2(*(__half2*)&u0.y); a0.z += f.x; a0.w += f.y;
    }
    a0.x += a1.x + a2.x + a3.x;
    a0.y += a1.y + a2.y + a3.y;
    a0.z += a1.z + a2.z + a3.z;
    a0.w += a1.w + a2.w + a3.w;
    const float s = g_inv[node];
    a0.x *= s; a0.y *= s; a0.z *= s; a0.w *= s;
    uint32_t h0, l0, h1, l1;
    split2(a0.x, a0.y, h0, l0);
    split2(a0.z, a0.w, h1, l1);
    uint32_t* out = (uint32_t*)g_aggs4;
    *(uint2*)(out + (size_t)node * 128 + lane * 2) = make_uint2(h0, h1);
    *(uint2*)(out + (size_t)node * 128 + 64 + lane * 2) = make_uint2(l0, l1);
}

// ---------------- tensor-core SAGE layer (mma.sync bf16) --------------------
// 8 warps in 4x2 grid: each warp 32 rows x 64 cols. 3-pairing hi/lo split.
#define RSW 132
#define A_WORDS (128 * RSW)
#define SMEM_WORDS (3 * A_WORDS)   // A, B0, B1 = 202.75KB

__global__ void __launch_bounds__(256, 1) sage_gemm_mma(
    int layer, int hs_in_sel, int do_split, int write16,
    const float* __restrict__ bl)
{
    extern __shared__ uint32_t smem[];
    uint32_t* As  = smem;
    uint32_t* B0s = smem + A_WORDS;
    uint32_t* B1s = smem + 2 * A_WORDS;

    const uint32_t* Ain0 = (const uint32_t*)g_aggs4;
    const uint32_t* Ain1 = hs_in_sel ? (const uint32_t*)g_hsB4 : (const uint32_t*)g_hsA4;
    uint32_t* hs_out = hs_in_sel ? (uint32_t*)g_hsA4 : (uint32_t*)g_hsB4;

    const int tid = threadIdx.x;
    const int wid = tid >> 5;
    const int lane = tid & 31;
    const int gid = lane >> 2;
    const int tig = lane & 3;
    const int wr = wid & 3;     // row group (32 rows)
    const int wc = wid >> 2;    // col half (64 cols)

    // Load all B (2 sources x 128 n x 128 words) into SMEM, padded rows.
    {
        const uint4* Bp = g_Bp4[layer];
#pragma unroll
        for (int i = 0; i < 32; i++) {
            int id = tid + 256 * i;          // 8192 uint4
            int s = id >> 12;
            int n = (id >> 5) & 127;
            int q = id & 31;
            uint4 v = Bp[id];
            uint32_t* dst = (s ? B1s : B0s) + n * RSW + q * 4;
            *(uint4*)dst = v;
        }
    }

    for (int tile = blockIdx.x; tile < NT; tile += gridDim.x) {
        const int mbase = tile * 128;
        float acc[2][8][4];
#pragma unroll
        for (int m = 0; m < 2; m++)
#pragma unroll
            for (int nf = 0; nf < 8; nf++)
#pragma unroll
                for (int i = 0; i < 4; i++) acc[m][nf][i] = 0.0f;

        for (int s = 0; s < 2; s++) {
            const uint32_t* Ag = s ? Ain1 : Ain0;
            const uint32_t* Bs = s ? B1s : B0s;
            __syncthreads();
#pragma unroll
            for (int i = 0; i < 16; i++) {
                int id = tid + 256 * i;
                int r = id >> 5;
                int q = id & 31;
                int grow = mbase + r;
                if (grow >= NN) grow = 0;
                uint4 v = *(const uint4*)(Ag + (size_t)grow * 128 + q * 4);
                *(uint4*)(As + r * RSW + q * 4) = v;
            }
            __syncthreads();

            const uint32_t* Aw = As + (wr * 32 + gid) * RSW + tig;
            const uint32_t* Bw = Bs + (wc * 64 + gid) * RSW + tig;
            for (int ks = 0; ks < 8; ks++) {
                const uint32_t* Ap = Aw + ks * 8;
                uint32_t ah[2][4], al[2][4];
#pragma unroll
                for (int m = 0; m < 2; m++) {
                    const uint32_t* Am = Ap + m * (16 * RSW);
                    ah[m][0] = Am[0];            ah[m][2] = Am[4];
                    ah[m][1] = Am[8 * RSW];      ah[m][3] = Am[8 * RSW + 4];
                    al[m][0] = Am[64];           al[m][2] = Am[68];
                    al[m][1] = Am[8 * RSW + 64]; al[m][3] = Am[8 * RSW + 68];
                }
                const uint32_t* Bq = Bw + ks * 8;
#pragma unroll
                for (int nf = 0; nf < 8; nf++) {
                    const uint32_t* Bn = Bq + nf * (8 * RSW);
                    uint32_t bh0 = Bn[0], bh1 = Bn[4];
                    uint32_t bl0 = Bn[64], bl1 = Bn[68];
#pragma unroll
                    for (int m = 0; m < 2; m++) {
                        mma_bf16(acc[m][nf], ah[m][0], ah[m][1], ah[m][2], ah[m][3], bh0, bh1);
                        mma_bf16(acc[m][nf], al[m][0], al[m][1], al[m][2], al[m][3], bh0, bh1);
                        mma_bf16(acc[m][nf], ah[m][0], ah[m][1], ah[m][2], ah[m][3], bl0, bl1);
                    }
                }
            }
        }

        // epilogue: bias + relu, then fp16 store (l0/l1) or fp32 store (l2),
        // plus optional hi/lo split store for the next GEMM.
#pragma unroll
        for (int m = 0; m < 2; m++) {
            const int r0 = mbase + wr * 32 + m * 16 + gid;
            const int r1 = r0 + 8;
#pragma unroll
            for (int nf = 0; nf < 8; nf++) {
                const int col = wc * 64 + nf * 8 + tig * 2;
                const float2 bb = *(const float2*)(bl + col);
                float v00 = fmaxf(acc[m][nf][0] + bb.x, 0.0f);
                float v01 = fmaxf(acc[m][nf][1] + bb.y, 0.0f);
                float v10 = fmaxf(acc[m][nf][2] + bb.x, 0.0f);
                float v11 = fmaxf(acc[m][nf][3] + bb.y, 0.0f);
                if (write16) {
                    if (r0 < NN) {
                        __half2 p = __floats2half2_rn(v00, v01);
                        *(uint32_t*)(g_h16 + (size_t)r0 * C + col) = *(uint32_t*)&p;
                    }
                    if (r1 < NN) {
                        __half2 p = __floats2half2_rn(v10, v11);
                        *(uint32_t*)(g_h16 + (size_t)r1 * C + col) = *(uint32_t*)&p;
                    }
                } else {
                    if (r0 < NN) *(float2*)(g_h0 + (size_t)r0 * C + col) = make_float2(v00, v01);
                    if (r1 < NN) *(float2*)(g_h0 + (size_t)r1 * C + col) = make_float2(v10, v11);
                }
                if (do_split) {
                    const int w = col >> 1;
                    uint32_t hi, lo;
                    if (r0 < NN) {
                        split2(v00, v01, hi, lo);
                        hs_out[(size_t)r0 * 128 + w] = hi;
                        hs_out[(size_t)r0 * 128 + 64 + w] = lo;
                    }
                    if (r1 < NN) {
                        split2(v10, v11, hi, lo);
                        hs_out[(size_t)r1 * 128 + w] = hi;
                        hs_out[(size_t)r1 * 128 + 64 + w] = lo;
                    }
                }
            }
        }
    }
}

// ---------------- global mean pool: run-length over sorted batch ------------
__global__ void pool_kernel() {
    int gid = blockIdx.x * blockDim.x + threadIdx.x;
    int warp = gid >> 5;
    int lane = gid & 31;
    int n0 = warp * 16;
    if (n0 >= NN) return;
    int cur = g_batch[n0];
    float4 acc = make_float4(0.f, 0.f, 0.f, 0.f);
    const int co = lane * 4;
#pragma unroll
    for (int k = 0; k < 16; k++) {
        int node = n0 + k;
        if (node >= NN) break;
        int b = g_batch[node];
        if (b != cur) {
            float* p = g_pool + cur * C + co;
            atomicAdd(p + 0, acc.x);
            atomicAdd(p + 1, acc.y);
            atomicAdd(p + 2, acc.z);
            atomicAdd(p + 3, acc.w);
            acc = make_float4(0.f, 0.f, 0.f, 0.f);
            cur = b;
        }
        const float4 v = *(const float4*)(g_h0 + (size_t)node * C + co);
        acc.x += v.x; acc.y += v.y; acc.z += v.z; acc.w += v.w;
    }
    float* p = g_pool + cur * C + co;
    atomicAdd(p + 0, acc.x);
    atomicAdd(p + 1, acc.y);
    atomicAdd(p + 2, acc.z);
    atomicAdd(p + 3, acc.w);
}

// ---------------- head ------------------------------------------------------
__global__ void out_kernel(const float* __restrict__ W_lin,
                           const float* __restrict__ b_lin,
                           float* __restrict__ out) {
    int g = blockIdx.x;
    int c = threadIdx.x;
    __shared__ float sv[C];
    sv[c] = g_pool[g * C + c] * g_ginv[g];
    __syncthreads();
    if (c < OUTC) {
        float s = b_lin[c];
#pragma unroll
        for (int k = 0; k < C; k++) s += sv[k] * W_lin[c * C + k];
        out[g * OUTC + c] = s;
    }
}

// ---------------- launch ----------------------------------------------------
extern "C" void kernel_launch(void* const* d_in, const int* in_sizes, int n_in,
                              void* d_out, int out_size) {
    const float* x      = (const float*)d_in[0];
    const void*  ei     = d_in[1];
    const void*  batch  = d_in[2];
    const float* Wl[3]  = {(const float*)d_in[3], (const float*)d_in[6], (const float*)d_in[9]};
    const float* blv[3] = {(const float*)d_in[4], (const float*)d_in[7], (const float*)d_in[10]};
    const float* Wr[3]  = {(const float*)d_in[5], (const float*)d_in[8], (const float*)d_in[11]};
    const float* W_lin  = (const float*)d_in[12];
    const float* b_lin  = (const float*)d_in[13];
    float* out = (float*)d_out;

    static int smem_set = 0;
    if (!smem_set) {
        cudaFuncSetAttribute(sage_gemm_mma,
                             cudaFuncAttributeMaxDynamicSharedMemorySize,
                             SMEM_WORDS * 4);
        smem_set = 1;
    }

    const int TB = 256;
    const int gE = (NE + TB - 1) / TB;       // 2344
    const int gN = (NN + TB - 1) / TB;       // 196
    const int gW = (NN * 32 + TB - 1) / TB;  // 6250
    const int gP = ((NN + 15) / 16 * 32 + TB - 1) / TB;  // 391

    detect_kernel<<<1, 1>>>((const unsigned int*)ei);
    zero_setup<<<gN, TB>>>();
    convert_fused<<<gE, TB>>>(ei, batch);
    scan1<<<gN, TB>>>();
    scan2<<<1, 256>>>();
    scan3<<<gN, TB>>>();
    fill_kernel<<<gE, TB>>>();

    prep_all<<<(3 * 16384 + TB - 1) / TB, TB>>>(Wl[0], Wr[0], Wl[1], Wr[1], Wl[2], Wr[2]);
    split_x<<<gW, TB>>>(x);

    // l0: gather(x16),  hs_in=A(x), split->B, h16 out
    // l1: gather(h16),  hs_in=B,    split->A, h16 out
    // l2: gather(h16),  hs_in=A,    no split, fp32 h0 out
    const int in_sel[3]  = {0, 1, 1};
    const int hs_sel[3]  = {0, 1, 0};
    const int do_spl[3]  = {1, 1, 0};
    const int wr16[3]    = {1, 1, 0};
    for (int l = 0; l < 3; l++) {
        gather_kernel<<<gW, TB>>>(in_sel[l]);
        sage_gemm_mma<<<148, TB, SMEM_WORDS * 4>>>(l, hs_sel[l], do_spl[l], wr16[l], blv[l]);
    }

    pool_kernel<<<gP, TB>>>();
    out_kernel<<<NG, C>>>(W_lin, b_lin, out);
}

// round 8
// speedup vs baseline: 1.4548x; 1.4548x over previous
#include <cuda_runtime.h>
#include <cuda_fp16.h>
#include <cstdint>
#include <cstddef>

#define NN   50000
#define NE   600000
#define C    128
#define NG   128
#define OUTC 10
#define NT   391          // ceil(NN/128) M-tiles
#define NCTA 148

// ---------------- scratch (static device globals: allocation-free) ----------
__device__ float  g_h0[NN * C];        // layer-2 fp32 output (for pool)
__device__ __half g_x16[NN * C];       // fp16 shadow of x
__device__ __half g_h16[NN * C];       // fp16 h (layers 0/1 out; gather+GEMM in)
__device__ __half g_agg16[NN * C];     // fp16 aggregated means
__device__ float  g_inv[NN];
__device__ float  g_ginv[NG];
__device__ float  g_pool[NG * C];
// weights fp16 split: [layer][src(2)][n(128)][128 u32 words: 0..63 hi, 64..127 lo]
__device__ uint4 g_Bp4[3][8192];
__device__ int   g_cnt[NN];
__device__ int   g_gcnt[NG];
__device__ int   g_off[NN + 1];
__device__ int   g_cur[NN];
__device__ int   g_adj[NE];
__device__ int   g_src[NE];
__device__ int   g_dst[NE];
__device__ int   g_batch[NN];
__device__ int   g_part[256];
__device__ int   g_pbase[256];
__device__ int   g_is64;

// ---------------- mma.sync fp16 m16n8k16, f32 accum --------------------------
__device__ __forceinline__ void mma_f16(float* d,
                                        uint32_t a0, uint32_t a1, uint32_t a2, uint32_t a3,
                                        uint32_t b0, uint32_t b1) {
    asm volatile(
        "mma.sync.aligned.m16n8k16.row.col.f32.f16.f16.f32 "
        "{%0,%1,%2,%3}, {%4,%5,%6,%7}, {%8,%9}, {%0,%1,%2,%3};"
        : "+f"(d[0]), "+f"(d[1]), "+f"(d[2]), "+f"(d[3])
        : "r"(a0), "r"(a1), "r"(a2), "r"(a3), "r"(b0), "r"(b1));
}

// ---------------- index dtype detection -------------------------------------
__global__ void detect_kernel(const unsigned int* __restrict__ ei_words) {
    int is64 = 1;
#pragma unroll
    for (int i = 0; i < 16; i++)
        if (ei_words[1 + 74 * i] != 0u) { is64 = 0; break; }
    g_is64 = is64;
}

// ---------------- zero pass --------------------------------------------------
__global__ void zero_setup() {
    int i = blockIdx.x * blockDim.x + threadIdx.x;
    if (i < NN) g_cnt[i] = 0;
    if (i < NG) g_gcnt[i] = 0;
    if (i < NG * C) g_pool[i] = 0.0f;
}

// ---------------- fused convert + degree + batch count ----------------------
__global__ void convert_fused(const void* __restrict__ ei, const void* __restrict__ batch) {
    int i = blockIdx.x * blockDim.x + threadIdx.x;
    const bool is64 = (g_is64 != 0);
    if (i < NE) {
        int s, d;
        if (is64) {
            const long long* p = (const long long*)ei;
            s = (int)p[i];
            d = (int)p[NE + i];
        } else {
            const int* p = (const int*)ei;
            s = p[i];
            d = p[NE + i];
        }
        g_src[i] = s;
        g_dst[i] = d;
        atomicAdd(&g_cnt[d], 1);
    }
    if (i < NN) {
        int b;
        if (is64) b = (int)((const long long*)batch)[i];
        else      b = ((const int*)batch)[i];
        g_batch[i] = b;
        atomicAdd(&g_gcnt[b], 1);
    }
}

// ---------------- 3-stage parallel scan --------------------------------------
__global__ void scan1() {
    __shared__ int red[256];
    const int tid = threadIdx.x;
    int i = blockIdx.x * 256 + tid;
    red[tid] = (i < NN) ? g_cnt[i] : 0;
    __syncthreads();
    for (int s = 128; s > 0; s >>= 1) {
        if (tid < s) red[tid] += red[tid + s];
        __syncthreads();
    }
    if (tid == 0) g_part[blockIdx.x] = red[0];
}

__global__ void scan2() {
    __shared__ int sc[256];
    const int t = threadIdx.x;
    int v = (t < 196) ? g_part[t] : 0;
    sc[t] = v;
    __syncthreads();
    for (int d = 1; d < 256; d <<= 1) {
        int val = sc[t];
        int add = (t >= d) ? sc[t - d] : 0;
        __syncthreads();
        sc[t] = val + add;
        __syncthreads();
    }
    if (t < 196) g_pbase[t] = sc[t] - v;
    if (t == 0) g_off[NN] = NE;
    if (t < NG) g_ginv[t] = 1.0f / fmaxf((float)g_gcnt[t], 1.0f);
}

__global__ void scan3() {
    __shared__ int sc[256];
    const int tid = threadIdx.x;
    int i = blockIdx.x * 256 + tid;
    int v = (i < NN) ? g_cnt[i] : 0;
    sc[tid] = v;
    __syncthreads();
    for (int d = 1; d < 256; d <<= 1) {
        int val = sc[tid];
        int add = (tid >= d) ? sc[tid - d] : 0;
        __syncthreads();
        sc[tid] = val + add;
        __syncthreads();
    }
    if (i < NN) {
        int excl = sc[tid] - v + g_pbase[blockIdx.x];
        g_off[i] = excl;
        g_cur[i] = excl;
        g_inv[i] = 1.0f / fmaxf((float)v, 1.0f);
    }
}

__global__ void fill_kernel() {
    int e = blockIdx.x * blockDim.x + threadIdx.x;
    if (e < NE) {
        int dst = g_dst[e];
        int pos = atomicAdd(&g_cur[dst], 1);
        g_adj[pos] = g_src[e];
    }
}

// ---------------- fused weight fp16-split + x fp16 convert -------------------
#define PREPN (3 * 16384)
__global__ void prep_split(const float* __restrict__ Wl0, const float* __restrict__ Wr0,
                           const float* __restrict__ Wl1, const float* __restrict__ Wr1,
                           const float* __restrict__ Wl2, const float* __restrict__ Wr2,
                           const float* __restrict__ x) {
    int id = blockIdx.x * blockDim.x + threadIdx.x;
    if (id < PREPN) {
        int layer = id >> 14;
        int rem = id & 16383;
        int s = rem >> 13;
        int n = (rem >> 6) & 127;
        int w = rem & 63;
        const float* W;
        if (layer == 0)      W = s ? Wr0 : Wl0;
        else if (layer == 1) W = s ? Wr1 : Wl1;
        else                 W = s ? Wr2 : Wl2;
        float a = W[n * 128 + 2 * w];
        float b = W[n * 128 + 2 * w + 1];
        __half ha = __float2half_rn(a), hb = __float2half_rn(b);
        float ra = a - __half2float(ha), rb = b - __half2float(hb);
        __half la = __float2half_rn(ra), lb = __float2half_rn(rb);
        __half2 hp = __halves2half2(ha, hb);
        __half2 lp = __halves2half2(la, lb);
        uint32_t* Bp = (uint32_t*)g_Bp4[layer];
        Bp[(s * 128 + n) * 128 + w]      = *(uint32_t*)&hp;
        Bp[(s * 128 + n) * 128 + 64 + w] = *(uint32_t*)&lp;
    } else {
        int j = id - PREPN;
        if (j < NN * 32) {
            int node = j >> 5;
            int f4 = j & 31;
            const float4 v = *(const float4*)(x + (size_t)node * C + f4 * 4);
            __half2 p0 = __floats2half2_rn(v.x, v.y);
            __half2 p1 = __floats2half2_rn(v.z, v.w);
            *(uint2*)(g_x16 + (size_t)node * C + f4 * 4) =
                make_uint2(*(uint32_t*)&p0, *(uint32_t*)&p1);
        }
    }
}

// ---------------- mean aggregation (fp16 in/out, unroll x4) ------------------
__global__ void gather_kernel(int in_sel) {
    const __half* hin = (in_sel == 0) ? g_x16 : g_h16;
    int gid = blockIdx.x * blockDim.x + threadIdx.x;
    int node = gid >> 5;
    int lane = gid & 31;
    if (node >= NN) return;
    const int beg = g_off[node];
    const int end = g_off[node + 1];
    const int co = lane * 4;
    float4 a0 = make_float4(0.f, 0.f, 0.f, 0.f);
    float4 a1 = make_float4(0.f, 0.f, 0.f, 0.f);
    float4 a2 = make_float4(0.f, 0.f, 0.f, 0.f);
    float4 a3 = make_float4(0.f, 0.f, 0.f, 0.f);
    int i = beg;
    const int n4 = beg + ((end - beg) & ~3);
    for (; i < n4; i += 4) {
        int s0 = g_adj[i], s1 = g_adj[i + 1], s2 = g_adj[i + 2], s3 = g_adj[i + 3];
        uint2 u0 = *(const uint2*)(hin + (size_t)s0 * C + co);
        uint2 u1 = *(const uint2*)(hin + (size_t)s1 * C + co);
        uint2 u2 = *(const uint2*)(hin + (size_t)s2 * C + co);
        uint2 u3 = *(const uint2*)(hin + (size_t)s3 * C + co);
        float2 f;
        f = __half22float2(*(__half2*)&u0.x); a0.x += f.x; a0.y += f.y;
        f = __half22float2(*(__half2*)&u0.y); a0.z += f.x; a0.w += f.y;
        f = __half22float2(*(__half2*)&u1.x); a1.x += f.x; a1.y += f.y;
        f = __half22float2(*(__half2*)&u1.y); a1.z += f.x; a1.w += f.y;
        f = __half22float2(*(__half2*)&u2.x); a2.x += f.x; a2.y += f.y;
        f = __half22float2(*(__half2*)&u2.y); a2.z += f.x; a2.w += f.y;
        f = __half22float2(*(__half2*)&u3.x); a3.x += f.x; a3.y += f.y;
        f = __half22float2(*(__half2*)&u3.y); a3.z += f.x; a3.w += f.y;
    }
    for (; i < end; i++) {
        int s0 = g_adj[i];
        uint2 u0 = *(const uint2*)(hin + (size_t)s0 * C + co);
        float2 f;
        f = __half22float2(*(__half2*)&u0.x); a0.x += f.x; a0.y += f.y;
        f = __half22float2(*(__half2*)&u0.y); a0.z += f.x; a0.w += f.y;
    }
    a0.x += a1.x + a2.x + a3.x;
    a0.y += a1.y + a2.y + a3.y;
    a0.z += a1.z + a2.z + a3.z;
    a0.w += a1.w + a2.w + a3.w;
    const float s = g_inv[node];
    __half2 p0 = __floats2half2_rn(a0.x * s, a0.y * s);
    __half2 p1 = __floats2half2_rn(a0.z * s, a0.w * s);
    *(uint2*)(g_agg16 + (size_t)node * C + co) =
        make_uint2(*(uint32_t*)&p0, *(uint32_t*)&p1);
}

// ---------------- tensor-core SAGE layer (fp16, 2-pairing, dbl-buffered A) ---
// A: plain fp16 [128 x 64 words], padded 68. B: fp16 hi/lo [128 x 132 words].
// 8 warps in 4x2 grid: warp = 32 rows x 64 cols.
#define RSA 68
#define A_WORDS (128 * RSA)        // 8704
#define RSB 132
#define B_WORDS (128 * RSB)        // 16896
#define SMEM_WORDS (2 * A_WORDS + 2 * B_WORDS)   // 51200 words = 200KB

__device__ __forceinline__ void lda_regs(uint4* v, const __half* src, int mbase, int tid) {
#pragma unroll
    for (int i = 0; i < 8; i++) {
        int id = tid + 256 * i;        // 2048 uint4
        int r = id >> 4;               // row 0..127
        int q = id & 15;               // uint4 in row
        int gr = mbase + r;
        if (gr >= NN) gr = 0;
        v[i] = *(const uint4*)(src + (size_t)gr * C + q * 8);
    }
}

__device__ __forceinline__ void sta_regs(uint32_t* As, const uint4* v, int tid) {
#pragma unroll
    for (int i = 0; i < 8; i++) {
        int id = tid + 256 * i;
        int r = id >> 4;
        int q = id & 15;
        *(uint4*)(As + r * RSA + q * 4) = v[i];
    }
}

__global__ void __launch_bounds__(256, 1) sage_gemm_mma(
    int layer, int write16, const float* __restrict__ bl)
{
    extern __shared__ uint32_t smem[];
    uint32_t* Asb[2] = {smem, smem + A_WORDS};
    uint32_t* B0s = smem + 2 * A_WORDS;
    uint32_t* B1s = B0s + B_WORDS;

    const __half* hsrc = (layer == 0) ? g_x16 : g_h16;

    const int tid = threadIdx.x;
    const int wid = tid >> 5;
    const int lane = tid & 31;
    const int gid = lane >> 2;
    const int tig = lane & 3;
    const int wr = wid & 3;     // row group (32 rows)
    const int wc = wid >> 2;    // col half (64 cols)

    // Load all B (2 sources x 128 n x 128 words), padded rows.
    {
        const uint4* Bp = g_Bp4[layer];
#pragma unroll
        for (int i = 0; i < 32; i++) {
            int id = tid + 256 * i;          // 8192 uint4
            int s = id >> 12;
            int n = (id >> 5) & 127;
            int q = id & 31;
            uint4 v = Bp[id];
            *(uint4*)((s ? B1s : B0s) + n * RSB + q * 4) = v;
        }
    }

    uint4 pf[8];
    // prologue: stage agg tile for first tile
    lda_regs(pf, g_agg16, blockIdx.x * 128, tid);
    sta_regs(Asb[0], pf, tid);
    __syncthreads();
    int cur = 0;

    for (int tile = blockIdx.x; tile < NT; tile += NCTA) {
        const int mbase = tile * 128;
        float acc[2][8][4];
#pragma unroll
        for (int m = 0; m < 2; m++)
#pragma unroll
            for (int nf = 0; nf < 8; nf++)
#pragma unroll
                for (int i = 0; i < 4; i++) acc[m][nf][i] = 0.0f;

        const int nt2 = tile + NCTA;
        const bool hasnext = (nt2 < NT);

#pragma unroll
        for (int s = 0; s < 2; s++) {
            // prefetch next A chunk while this chunk's MMA runs
            if (s == 0) lda_regs(pf, hsrc, mbase, tid);
            else if (hasnext) lda_regs(pf, g_agg16, nt2 * 128, tid);

            const uint32_t* As = Asb[cur];
            const uint32_t* Bs = s ? B1s : B0s;
            const uint32_t* Aw = As + (wr * 32 + gid) * RSA + tig;
            const uint32_t* Bw = Bs + (wc * 64 + gid) * RSB + tig;
#pragma unroll
            for (int ks = 0; ks < 8; ks++) {
                uint32_t ah[2][4];
#pragma unroll
                for (int m = 0; m < 2; m++) {
                    const uint32_t* Am = Aw + (m * 16) * RSA + ks * 8;
                    ah[m][0] = Am[0];
                    ah[m][1] = Am[8 * RSA];
                    ah[m][2] = Am[4];
                    ah[m][3] = Am[8 * RSA + 4];
                }
                const uint32_t* Bq = Bw + ks * 8;
#pragma unroll
                for (int nf = 0; nf < 8; nf++) {
                    const uint32_t* Bn = Bq + nf * (8 * RSB);
                    uint32_t bh0 = Bn[0], bh1 = Bn[4];
                    uint32_t bl0 = Bn[64], bl1 = Bn[68];
#pragma unroll
                    for (int m = 0; m < 2; m++) {
                        mma_f16(acc[m][nf], ah[m][0], ah[m][1], ah[m][2], ah[m][3], bh0, bh1);
                        mma_f16(acc[m][nf], ah[m][0], ah[m][1], ah[m][2], ah[m][3], bl0, bl1);
                    }
                }
            }

            if (s == 1) {
                // epilogue: bias + relu; fp16 h (l0/l1) or fp32 h0 (l2)
#pragma unroll
                for (int m = 0; m < 2; m++) {
                    const int r0 = mbase + wr * 32 + m * 16 + gid;
                    const int r1 = r0 + 8;
#pragma unroll
                    for (int nf = 0; nf < 8; nf++) {
                        const int col = wc * 64 + nf * 8 + tig * 2;
                        const float2 bb = *(const float2*)(bl + col);
                        float v00 = fmaxf(acc[m][nf][0] + bb.x, 0.0f);
                        float v01 = fmaxf(acc[m][nf][1] + bb.y, 0.0f);
                        float v10 = fmaxf(acc[m][nf][2] + bb.x, 0.0f);
                        float v11 = fmaxf(acc[m][nf][3] + bb.y, 0.0f);
                        if (write16) {
                            if (r0 < NN) {
                                __half2 p = __floats2half2_rn(v00, v01);
                                *(uint32_t*)(g_h16 + (size_t)r0 * C + col) = *(uint32_t*)&p;
                            }
                            if (r1 < NN) {
                                __half2 p = __floats2half2_rn(v10, v11);
                                *(uint32_t*)(g_h16 + (size_t)r1 * C + col) = *(uint32_t*)&p;
                            }
                        } else {
                            if (r0 < NN) *(float2*)(g_h0 + (size_t)r0 * C + col) = make_float2(v00, v01);
                            if (r1 < NN) *(float2*)(g_h0 + (size_t)r1 * C + col) = make_float2(v10, v11);
                        }
                    }
                }
            }

            // store prefetched chunk into the other buffer
            if (s == 0 || hasnext) sta_regs(Asb[cur ^ 1], pf, tid);
            __syncthreads();
            cur ^= 1;
        }
    }
}

// ---------------- global mean pool: run-length over sorted batch ------------
__global__ void pool_kernel() {
    int gid = blockIdx.x * blockDim.x + threadIdx.x;
    int warp = gid >> 5;
    int lane = gid & 31;
    int n0 = warp * 16;
    if (n0 >= NN) return;
    int cur = g_batch[n0];
    float4 acc = make_float4(0.f, 0.f, 0.f, 0.f);
    const int co = lane * 4;
#pragma unroll
    for (int k = 0; k < 16; k++) {
        int node = n0 + k;
        if (node >= NN) break;
        int b = g_batch[node];
        if (b != cur) {
            float* p = g_pool + cur * C + co;
            atomicAdd(p + 0, acc.x);
            atomicAdd(p + 1, acc.y);
            atomicAdd(p + 2, acc.z);
            atomicAdd(p + 3, acc.w);
            acc = make_float4(0.f, 0.f, 0.f, 0.f);
            cur = b;
        }
        const float4 v = *(const float4*)(g_h0 + (size_t)node * C + co);
        acc.x += v.x; acc.y += v.y; acc.z += v.z; acc.w += v.w;
    }
    float* p = g_pool + cur * C + co;
    atomicAdd(p + 0, acc.x);
    atomicAdd(p + 1, acc.y);
    atomicAdd(p + 2, acc.z);
    atomicAdd(p + 3, acc.w);
}

// ---------------- head ------------------------------------------------------
__global__ void out_kernel(const float* __restrict__ W_lin,
                           const float* __restrict__ b_lin,
                           float* __restrict__ out) {
    int g = blockIdx.x;
    int c = threadIdx.x;
    __shared__ float sv[C];
    sv[c] = g_pool[g * C + c] * g_ginv[g];
    __syncthreads();
    if (c < OUTC) {
        float s = b_lin[c];
#pragma unroll
        for (int k = 0; k < C; k++) s += sv[k] * W_lin[c * C + k];
        out[g * OUTC + c] = s;
    }
}

// ---------------- launch ----------------------------------------------------
extern "C" void kernel_launch(void* const* d_in, const int* in_sizes, int n_in,
                              void* d_out, int out_size) {
    const float* x      = (const float*)d_in[0];
    const void*  ei     = d_in[1];
    const void*  batch  = d_in[2];
    const float* Wl[3]  = {(const float*)d_in[3], (const float*)d_in[6], (const float*)d_in[9]};
    const float* blv[3] = {(const float*)d_in[4], (const float*)d_in[7], (const float*)d_in[10]};
    const float* Wr[3]  = {(const float*)d_in[5], (const float*)d_in[8], (const float*)d_in[11]};
    const float* W_lin  = (const float*)d_in[12];
    const float* b_lin  = (const float*)d_in[13];
    float* out = (float*)d_out;

    static int smem_set = 0;
    if (!smem_set) {
        cudaFuncSetAttribute(sage_gemm_mma,
                             cudaFuncAttributeMaxDynamicSharedMemorySize,
                             SMEM_WORDS * 4);
        smem_set = 1;
    }

    const int TB = 256;
    const int gE = (NE + TB - 1) / TB;       // 2344
    const int gN = (NN + TB - 1) / TB;       // 196
    const int gW = (NN * 32 + TB - 1) / TB;  // 6250
    const int gP = ((NN + 15) / 16 * 32 + TB - 1) / TB;  // 391
    const int gS = (PREPN + NN * 32 + TB - 1) / TB;      // prep+split merged

    detect_kernel<<<1, 1>>>((const unsigned int*)ei);
    zero_setup<<<gN, TB>>>();
    convert_fused<<<gE, TB>>>(ei, batch);
    scan1<<<gN, TB>>>();
    scan2<<<1, 256>>>();
    scan3<<<gN, TB>>>();
    fill_kernel<<<gE, TB>>>();
    prep_split<<<gS, TB>>>(Wl[0], Wr[0], Wl[1], Wr[1], Wl[2], Wr[2], x);

    // l0: gather(x16) -> agg16; gemm(agg16, x16)  -> h16
    // l1: gather(h16) -> agg16; gemm(agg16, h16)  -> h16
    // l2: gather(h16) -> agg16; gemm(agg16, h16)  -> h0 (fp32)
    const int in_sel[3] = {0, 1, 1};
    const int wr16[3]   = {1, 1, 0};
    for (int l = 0; l < 3; l++) {
        gather_kernel<<<gW, TB>>>(in_sel[l]);
        sage_gemm_mma<<<NCTA, TB, SMEM_WORDS * 4>>>(l, wr16[l], blv[l]);
    }

    pool_kernel<<<gP, TB>>>();
    out_kernel<<<NG, C>>>(W_lin, b_lin, out);
}

// round 10
// speedup vs baseline: 1.4762x; 1.0147x over previous
#include <cuda_runtime.h>
#include <cuda_fp16.h>
#include <cstdint>
#include <cstddef>

#define NN   50000
#define NE   600000
#define C    128
#define NG   128
#define OUTC 10
#define NT   391          // ceil(NN/128) M-tiles
#define NCTA 148

// ---------------- scratch (static device globals: allocation-free) ----------
__device__ __half g_x16[NN * C];       // fp16 shadow of x
__device__ __half g_h16[NN * C];       // fp16 h (all layers out; gather+GEMM+pool in)
__device__ __half g_agg16[NN * C];     // fp16 aggregated means
__device__ float  g_inv[NN];
__device__ float  g_ginv[NG];
__device__ float  g_pool[NG * C];
// weights fp16 split: [layer][src(2)][n(128)][128 u32 words: 0..63 hi, 64..127 lo]
__device__ uint4 g_Bp4[3][8192];
__device__ int   g_cnt[NN];
__device__ int   g_gcnt[NG];
__device__ int   g_off[NN + 1];
__device__ int   g_cur[NN];
__device__ int   g_adj[NE];
__device__ int   g_batch[NN];
__device__ int   g_part[256];
__device__ int   g_pbase[256];
__device__ int   g_is64;

// ---------------- mma.sync fp16 m16n8k16, f32 accum --------------------------
__device__ __forceinline__ void mma_f16(float* d,
                                        uint32_t a0, uint32_t a1, uint32_t a2, uint32_t a3,
                                        uint32_t b0, uint32_t b1) {
    asm volatile(
        "mma.sync.aligned.m16n8k16.row.col.f32.f16.f16.f32 "
        "{%0,%1,%2,%3}, {%4,%5,%6,%7}, {%8,%9}, {%0,%1,%2,%3};"
        : "+f"(d[0]), "+f"(d[1]), "+f"(d[2]), "+f"(d[3])
        : "r"(a0), "r"(a1), "r"(a2), "r"(a3), "r"(b0), "r"(b1));
}

// ---------------- zero pass + index dtype detection --------------------------
__global__ void zero_detect(const unsigned int* __restrict__ ei_words) {
    int i = blockIdx.x * blockDim.x + threadIdx.x;
    if (i == 0) {
        int is64 = 1;
#pragma unroll
        for (int k = 0; k < 16; k++)
            if (ei_words[1 + 74 * k] != 0u) { is64 = 0; break; }
        g_is64 = is64;
    }
    if (i < NN) g_cnt[i] = 0;
    if (i < NG) g_gcnt[i] = 0;
    if (i < NG * C) g_pool[i] = 0.0f;
}

// ---------------- degree + batch count (reads dst half of ei only) ----------
__global__ void count_kernel(const void* __restrict__ ei, const void* __restrict__ batch) {
    int i = blockIdx.x * blockDim.x + threadIdx.x;
    const bool is64 = (g_is64 != 0);
    if (i < NE) {
        int d;
        if (is64) d = (int)((const long long*)ei)[NE + i];
        else      d = ((const int*)ei)[NE + i];
        atomicAdd(&g_cnt[d], 1);
    }
    if (i < NN) {
        int b;
        if (is64) b = (int)((const long long*)batch)[i];
        else      b = ((const int*)batch)[i];
        g_batch[i] = b;
        atomicAdd(&g_gcnt[b], 1);
    }
}

// ---------------- 3-stage parallel scan --------------------------------------
__global__ void scan1() {
    __shared__ int red[256];
    const int tid = threadIdx.x;
    int i = blockIdx.x * 256 + tid;
    red[tid] = (i < NN) ? g_cnt[i] : 0;
    __syncthreads();
    for (int s = 128; s > 0; s >>= 1) {
        if (tid < s) red[tid] += red[tid + s];
        __syncthreads();
    }
    if (tid == 0) g_part[blockIdx.x] = red[0];
}

__global__ void scan2() {
    __shared__ int sc[256];
    const int t = threadIdx.x;
    int v = (t < 196) ? g_part[t] : 0;
    sc[t] = v;
    __syncthreads();
    for (int d = 1; d < 256; d <<= 1) {
        int val = sc[t];
        int add = (t >= d) ? sc[t - d] : 0;
        __syncthreads();
        sc[t] = val + add;
        __syncthreads();
    }
    if (t < 196) g_pbase[t] = sc[t] - v;
    if (t == 0) g_off[NN] = NE;
    if (t < NG) g_ginv[t] = 1.0f / fmaxf((float)g_gcnt[t], 1.0f);
}

__global__ void scan3() {
    __shared__ int sc[256];
    const int tid = threadIdx.x;
    int i = blockIdx.x * 256 + tid;
    int v = (i < NN) ? g_cnt[i] : 0;
    sc[tid] = v;
    __syncthreads();
    for (int d = 1; d < 256; d <<= 1) {
        int val = sc[tid];
        int add = (tid >= d) ? sc[tid - d] : 0;
        __syncthreads();
        sc[tid] = val + add;
        __syncthreads();
    }
    if (i < NN) {
        int excl = sc[tid] - v + g_pbase[blockIdx.x];
        g_off[i] = excl;
        g_cur[i] = excl;
        g_inv[i] = 1.0f / fmaxf((float)v, 1.0f);
    }
}

// ---------------- CSR fill (reads ei directly) -------------------------------
__global__ void fill_kernel(const void* __restrict__ ei) {
    int e = blockIdx.x * blockDim.x + threadIdx.x;
    if (e < NE) {
        int s, d;
        if (g_is64) {
            const long long* p = (const long long*)ei;
            s = (int)p[e];
            d = (int)p[NE + e];
        } else {
            const int* p = (const int*)ei;
            s = p[e];
            d = p[NE + e];
        }
        int pos = atomicAdd(&g_cur[d], 1);
        g_adj[pos] = s;
    }
}

// ---------------- fused weight fp16-split + x fp16 convert -------------------
#define PREPN (3 * 16384)
__global__ void prep_split(const float* __restrict__ Wl0, const float* __restrict__ Wr0,
                           const float* __restrict__ Wl1, const float* __restrict__ Wr1,
                           const float* __restrict__ Wl2, const float* __restrict__ Wr2,
                           const float* __restrict__ x) {
    int id = blockIdx.x * blockDim.x + threadIdx.x;
    if (id < PREPN) {
        int layer = id >> 14;
        int rem = id & 16383;
        int s = rem >> 13;
        int n = (rem >> 6) & 127;
        int w = rem & 63;
        const float* W;
        if (layer == 0)      W = s ? Wr0 : Wl0;
        else if (layer == 1) W = s ? Wr1 : Wl1;
        else                 W = s ? Wr2 : Wl2;
        float a = W[n * 128 + 2 * w];
        float b = W[n * 128 + 2 * w + 1];
        __half ha = __float2half_rn(a), hb = __float2half_rn(b);
        float ra = a - __half2float(ha), rb = b - __half2float(hb);
        __half la = __float2half_rn(ra), lb = __float2half_rn(rb);
        __half2 hp = __halves2half2(ha, hb);
        __half2 lp = __halves2half2(la, lb);
        uint32_t* Bp = (uint32_t*)g_Bp4[layer];
        Bp[(s * 128 + n) * 128 + w]      = *(uint32_t*)&hp;
        Bp[(s * 128 + n) * 128 + 64 + w] = *(uint32_t*)&lp;
    } else {
        int j = id - PREPN;
        if (j < NN * 32) {
            int node = j >> 5;
            int f4 = j & 31;
            const float4 v = *(const float4*)(x + (size_t)node * C + f4 * 4);
            __half2 p0 = __floats2half2_rn(v.x, v.y);
            __half2 p1 = __floats2half2_rn(v.z, v.w);
            *(uint2*)(g_x16 + (size_t)node * C + f4 * 4) =
                make_uint2(*(uint32_t*)&p0, *(uint32_t*)&p1);
        }
    }
}

// ---------------- mean aggregation (fp16 in/out, unroll x8, MLP=8) ----------
__global__ void gather_kernel(int in_sel) {
    const __half* hin = (in_sel == 0) ? g_x16 : g_h16;
    int gid = blockIdx.x * blockDim.x + threadIdx.x;
    int node = gid >> 5;
    int lane = gid & 31;
    if (node >= NN) return;
    const int beg = g_off[node];
    const int end = g_off[node + 1];
    const int co = lane * 4;
    float4 ac[8];
#pragma unroll
    for (int k = 0; k < 8; k++) ac[k] = make_float4(0.f, 0.f, 0.f, 0.f);
    int i = beg;
    const int n8 = beg + ((end - beg) & ~7);
    for (; i < n8; i += 8) {
        int sx[8];
#pragma unroll
        for (int k = 0; k < 8; k++) sx[k] = g_adj[i + k];
        uint2 u[8];
#pragma unroll
        for (int k = 0; k < 8; k++) u[k] = *(const uint2*)(hin + (size_t)sx[k] * C + co);
#pragma unroll
        for (int k = 0; k < 8; k++) {
            float2 f0 = __half22float2(*(__half2*)&u[k].x);
            float2 f1 = __half22float2(*(__half2*)&u[k].y);
            ac[k].x += f0.x; ac[k].y += f0.y; ac[k].z += f1.x; ac[k].w += f1.y;
        }
    }
    for (; i < end; i++) {
        int s0 = g_adj[i];
        uint2 u0 = *(const uint2*)(hin + (size_t)s0 * C + co);
        float2 f0 = __half22float2(*(__half2*)&u0.x);
        float2 f1 = __half22float2(*(__half2*)&u0.y);
        ac[0].x += f0.x; ac[0].y += f0.y; ac[0].z += f1.x; ac[0].w += f1.y;
    }
#pragma unroll
    for (int k = 1; k < 8; k++) {
        ac[0].x += ac[k].x; ac[0].y += ac[k].y;
        ac[0].z += ac[k].z; ac[0].w += ac[k].w;
    }
    const float s = g_inv[node];
    __half2 p0 = __floats2half2_rn(ac[0].x * s, ac[0].y * s);
    __half2 p1 = __floats2half2_rn(ac[0].z * s, ac[0].w * s);
    *(uint2*)(g_agg16 + (size_t)node * C + co) =
        make_uint2(*(uint32_t*)&p0, *(uint32_t*)&p1);
}

// ---------------- tensor-core SAGE layer (fp16, 2-pairing, dbl-buffered A) ---
// A: plain fp16 [128 x 64 words], padded 68. B: fp16 hi/lo [128 x 132 words].
// 8 warps in 4x2 grid: warp = 32 rows x 64 cols. Output always fp16 h16.
#define RSA 68
#define A_WORDS (128 * RSA)        // 8704
#define RSB 132
#define B_WORDS (128 * RSB)        // 16896
#define SMEM_WORDS (2 * A_WORDS + 2 * B_WORDS)   // 51200 words = 200KB

__device__ __forceinline__ void lda_regs(uint4* v, const __half* src, int mbase, int tid) {
#pragma unroll
    for (int i = 0; i < 8; i++) {
        int id = tid + 256 * i;        // 2048 uint4
        int r = id >> 4;               // row 0..127
        int q = id & 15;               // uint4 in row
        int gr = mbase + r;
        if (gr >= NN) gr = 0;
        v[i] = *(const uint4*)(src + (size_t)gr * C + q * 8);
    }
}

__device__ __forceinline__ void sta_regs(uint32_t* As, const uint4* v, int tid) {
#pragma unroll
    for (int i = 0; i < 8; i++) {
        int id = tid + 256 * i;
        int r = id >> 4;
        int q = id & 15;
        *(uint4*)(As + r * RSA + q * 4) = v[i];
    }
}

__global__ void __launch_bounds__(256, 1) sage_gemm_mma(
    int layer, const float* __restrict__ bl)
{
    extern __shared__ uint32_t smem[];
    uint32_t* Asb[2] = {smem, smem + A_WORDS};
    uint32_t* B0s = smem + 2 * A_WORDS;
    uint32_t* B1s = B0s + B_WORDS;

    const __half* hsrc = (layer == 0) ? g_x16 : g_h16;

    const int tid = threadIdx.x;
    const int wid = tid >> 5;
    const int lane = tid & 31;
    const int gid = lane >> 2;
    const int tig = lane & 3;
    const int wr = wid & 3;     // row group (32 rows)
    const int wc = wid >> 2;    // col half (64 cols)

    // Load all B (2 sources x 128 n x 128 words), padded rows.
    {
        const uint4* Bp = g_Bp4[layer];
#pragma unroll
        for (int i = 0; i < 32; i++) {
            int id = tid + 256 * i;          // 8192 uint4
            int s = id >> 12;
            int n = (id >> 5) & 127;
            int q = id & 31;
            uint4 v = Bp[id];
            *(uint4*)((s ? B1s : B0s) + n * RSB + q * 4) = v;
        }
    }

    uint4 pf[8];
    // prologue: stage agg tile for first tile
    lda_regs(pf, g_agg16, blockIdx.x * 128, tid);
    sta_regs(Asb[0], pf, tid);
    __syncthreads();
    int cur = 0;

    for (int tile = blockIdx.x; tile < NT; tile += NCTA) {
        const int mbase = tile * 128;
        float acc[2][8][4];
#pragma unroll
        for (int m = 0; m < 2; m++)
#pragma unroll
            for (int nf = 0; nf < 8; nf++)
#pragma unroll
                for (int i = 0; i < 4; i++) acc[m][nf][i] = 0.0f;

        const int nt2 = tile + NCTA;
        const bool hasnext = (nt2 < NT);

#pragma unroll
        for (int s = 0; s < 2; s++) {
            // prefetch next A chunk while this chunk's MMA runs
            if (s == 0) lda_regs(pf, hsrc, mbase, tid);
            else if (hasnext) lda_regs(pf, g_agg16, nt2 * 128, tid);

            const uint32_t* As = Asb[cur];
            const uint32_t* Bs = s ? B1s : B0s;
            const uint32_t* Aw = As + (wr * 32 + gid) * RSA + tig;
            const uint32_t* Bw = Bs + (wc * 64 + gid) * RSB + tig;
#pragma unroll
            for (int ks = 0; ks < 8; ks++) {
                uint32_t ah[2][4];
#pragma unroll
                for (int m = 0; m < 2; m++) {
                    const uint32_t* Am = Aw + (m * 16) * RSA + ks * 8;
                    ah[m][0] = Am[0];
                    ah[m][1] = Am[8 * RSA];
                    ah[m][2] = Am[4];
                    ah[m][3] = Am[8 * RSA + 4];
                }
                const uint32_t* Bq = Bw + ks * 8;
#pragma unroll
                for (int nf = 0; nf < 8; nf++) {
                    const uint32_t* Bn = Bq + nf * (8 * RSB);
                    uint32_t bh0 = Bn[0], bh1 = Bn[4];
                    uint32_t bl0 = Bn[64], bl1 = Bn[68];
#pragma unroll
                    for (int m = 0; m < 2; m++) {
                        mma_f16(acc[m][nf], ah[m][0], ah[m][1], ah[m][2], ah[m][3], bh0, bh1);
                        mma_f16(acc[m][nf], ah[m][0], ah[m][1], ah[m][2], ah[m][3], bl0, bl1);
                    }
                }
            }

            if (s == 1) {
                // epilogue: bias + relu -> fp16 h16
#pragma unroll
                for (int m = 0; m < 2; m++) {
                    const int r0 = mbase + wr * 32 + m * 16 + gid;
                    const int r1 = r0 + 8;
#pragma unroll
                    for (int nf = 0; nf < 8; nf++) {
                        const int col = wc * 64 + nf * 8 + tig * 2;
                        const float2 bb = *(const float2*)(bl + col);
                        float v00 = fmaxf(acc[m][nf][0] + bb.x, 0.0f);
                        float v01 = fmaxf(acc[m][nf][1] + bb.y, 0.0f);
                        float v10 = fmaxf(acc[m][nf][2] + bb.x, 0.0f);
                        float v11 = fmaxf(acc[m][nf][3] + bb.y, 0.0f);
                        if (r0 < NN) {
                            __half2 p = __floats2half2_rn(v00, v01);
                            *(uint32_t*)(g_h16 + (size_t)r0 * C + col) = *(uint32_t*)&p;
                        }
                        if (r1 < NN) {
                            __half2 p = __floats2half2_rn(v10, v11);
                            *(uint32_t*)(g_h16 + (size_t)r1 * C + col) = *(uint32_t*)&p;
                        }
                    }
                }
            }

            // store prefetched chunk into the other buffer
            if (s == 0 || hasnext) sta_regs(Asb[cur ^ 1], pf, tid);
            __syncthreads();
            cur ^= 1;
        }
    }
}

// ---------------- global mean pool: run-length over sorted batch (fp16 in) --
__global__ void pool_kernel() {
    int gid = blockIdx.x * blockDim.x + threadIdx.x;
    int warp = gid >> 5;
    int lane = gid & 31;
    int n0 = warp * 16;
    if (n0 >= NN) return;
    int cur = g_batch[n0];
    float4 acc = make_float4(0.f, 0.f, 0.f, 0.f);
    const int co = lane * 4;
#pragma unroll
    for (int k = 0; k < 16; k++) {
        int node = n0 + k;
        if (node >= NN) break;
        int b = g_batch[node];
        if (b != cur) {
            float* p = g_pool + cur * C + co;
            atomicAdd(p + 0, acc.x);
            atomicAdd(p + 1, acc.y);
            atomicAdd(p + 2, acc.z);
            atomicAdd(p + 3, acc.w);
            acc = make_float4(0.f, 0.f, 0.f, 0.f);
            cur = b;
        }
        uint2 u = *(const uint2*)(g_h16 + (size_t)node * C + co);
        float2 f0 = __half22float2(*(__half2*)&u.x);
        float2 f1 = __half22float2(*(__half2*)&u.y);
        acc.x += f0.x; acc.y += f0.y; acc.z += f1.x; acc.w += f1.y;
    }
    float* p = g_pool + cur * C + co;
    atomicAdd(p + 0, acc.x);
    atomicAdd(p + 1, acc.y);
    atomicAdd(p + 2, acc.z);
    atomicAdd(p + 3, acc.w);
}

// ---------------- head ------------------------------------------------------
__global__ void out_kernel(const float* __restrict__ W_lin,
                           const float* __restrict__ b_lin,
                           float* __restrict__ out) {
    int g = blockIdx.x;
    int c = threadIdx.x;
    __shared__ float sv[C];
    sv[c] = g_pool[g * C + c] * g_ginv[g];
    __syncthreads();
    if (c < OUTC) {
        float s = b_lin[c];
#pragma unroll
        for (int k = 0; k < C; k++) s += sv[k] * W_lin[c * C + k];
        out[g * OUTC + c] = s;
    }
}

// ---------------- launch ----------------------------------------------------
extern "C" void kernel_launch(void* const* d_in, const int* in_sizes, int n_in,
                              void* d_out, int out_size) {
    const float* x      = (const float*)d_in[0];
    const void*  ei     = d_in[1];
    const void*  batch  = d_in[2];
    const float* Wl[3]  = {(const float*)d_in[3], (const float*)d_in[6], (const float*)d_in[9]};
    const float* blv[3] = {(const float*)d_in[4], (const float*)d_in[7], (const float*)d_in[10]};
    const float* Wr[3]  = {(const float*)d_in[5], (const float*)d_in[8], (const float*)d_in[11]};
    const float* W_lin  = (const float*)d_in[12];
    const float* b_lin  = (const float*)d_in[13];
    float* out = (float*)d_out;

    static int smem_set = 0;
    if (!smem_set) {
        cudaFuncSetAttribute(sage_gemm_mma,
                             cudaFuncAttributeMaxDynamicSharedMemorySize,
                             SMEM_WORDS * 4);
        smem_set = 1;
    }

    const int TB = 256;
    const int gE = (NE + TB - 1) / TB;       // 2344
    const int gN = (NN + TB - 1) / TB;       // 196
    const int gW = (NN * 32 + TB - 1) / TB;  // 6250
    const int gP = ((NN + 15) / 16 * 32 + TB - 1) / TB;  // 391
    const int gS = (PREPN + NN * 32 + TB - 1) / TB;

    zero_detect<<<gN, TB>>>((const unsigned int*)ei);
    count_kernel<<<gE, TB>>>(ei, batch);
    scan1<<<gN, TB>>>();
    scan2<<<1, 256>>>();
    scan3<<<gN, TB>>>();
    fill_kernel<<<gE, TB>>>(ei);
    prep_split<<<gS, TB>>>(Wl[0], Wr[0], Wl[1], Wr[1], Wl[2], Wr[2], x);

    // l: gather(h16|x16) -> agg16; gemm(agg16, hin) -> h16
    const int in_sel[3] = {0, 1, 1};
    for (int l = 0; l < 3; l++) {
        gather_kernel<<<gW, TB>>>(in_sel[l]);
        sage_gemm_mma<<<NCTA, TB, SMEM_WORDS * 4>>>(l, blv[l]);
    }

    pool_kernel<<<gP, TB>>>();
    out_kernel<<<NG, C>>>(W_lin, b_lin, out);
}